// round 17
// baseline (speedup 1.0000x reference)
#include <cuda_runtime.h>

// HawkesKT — table-collapsed; bf16-bit-packed table (no F2F in the inner loop).
// Table entry: uint32 = bf16(ga) << 16 | bf16(d),  d = -(beta-1)/ln5.
// Inner: sum_{i<j} ga * 2^((d - 1/ln5) * log2(|ti-tj| + 1e-10))  (1 LG2 + 1 EX2 per pair;
// unpack via LOP3/SHF bit tricks — ALU pipe, not the XU conversion pipe).

#define NJ  32         // j-columns per CTA
#define RSJ 515        // Gs row stride in uint32 units: bank=(3*tj+e)%32, conflict-free
#define THREADS 512

__device__ unsigned int g_pack[256 * 512];   // [c][e] -> packed (ga, d)

__device__ __forceinline__ float fast_ex2(float x) {
    float r;
    asm("ex2.approx.f32 %0, %1;" : "=f"(r) : "f"(x));
    return r;
}

__device__ __forceinline__ unsigned int f2bf_bits(float x) {   // round-to-nearest-even bf16
    unsigned int u = __float_as_uint(x);
    return (u + 0x7FFFu + ((u >> 16) & 1u)) >> 16;
}

// ---------------- Precompute: coalesced shuffle-GEMV into packed table ----------------
// 256 CTAs x 256 thr; CTA owns 2 e-rows. Lanes split the 64-dim dot (d4 = tid&15),
// 16 concepts per pass, unroll-4 for load MLP.
__global__ __launch_bounds__(256)
void precompute_kernel(const float* __restrict__ a_inter,    // [512,64]
                       const float* __restrict__ a_concept,  // [256,64]
                       const float* __restrict__ b_inter,    // [512,64]
                       const float* __restrict__ b_concept)  // [256,64]
{
    const int e0 = blockIdx.x * 2;
    const int tid = threadIdx.x;
    const int d4 = tid & 15;       // which float4 of the 64-dim row
    const int cl = tid >> 4;       // c_local 0..15

    float4 ai_r[2], bi_r[2];       // this lane's slice of the 2 e-rows
    #pragma unroll
    for (int e = 0; e < 2; e++) {
        ai_r[e] = ((const float4*)a_inter)[(e0 + e) * 16 + d4];
        bi_r[e] = ((const float4*)b_inter)[(e0 + e) * 16 + d4];
    }

    #pragma unroll 4
    for (int p = 0; p < 16; p++) {
        int c = p * 16 + cl;
        float4 av = ((const float4*)a_concept)[c * 16 + d4];   // coalesced
        float4 bv = ((const float4*)b_concept)[c * 16 + d4];

        float pa[2], pb[2];
        #pragma unroll
        for (int e = 0; e < 2; e++) {
            pa[e] = fmaf(av.x, ai_r[e].x, fmaf(av.y, ai_r[e].y,
                    fmaf(av.z, ai_r[e].z, av.w * ai_r[e].w)));
            pb[e] = fmaf(bv.x, bi_r[e].x, fmaf(bv.y, bi_r[e].y,
                    fmaf(bv.z, bi_r[e].z, bv.w * bi_r[e].w)));
        }
        #pragma unroll
        for (int m = 1; m < 16; m <<= 1) {
            #pragma unroll
            for (int e = 0; e < 2; e++) {
                pa[e] += __shfl_xor_sync(0xffffffffu, pa[e], m, 16);
                pb[e] += __shfl_xor_sync(0xffffffffu, pb[e], m, 16);
            }
        }
        if (d4 == 0) {
            #pragma unroll
            for (int e = 0; e < 2; e++) {
                float beta = fminf(fmaxf(pb[e] + 1.0f, 0.0f), 10.0f);
                float d    = -0.62133497f * (beta - 1.0f);   // small delta -> bf16-safe
                g_pack[c * 512 + e0 + e] = (f2bf_bits(pa[e]) << 16) | f2bf_bits(d);
            }
        }
    }
}

// ---------------- Main: causal elementwise sum ----------------
__global__ __launch_bounds__(THREADS, 3)
void hawkes_main(const int* __restrict__ concept_seq,      // [32,1024]
                 const int* __restrict__ question_seq,     // [32,1024]
                 const int* __restrict__ correctness_seq,  // [32,1024]
                 const int* __restrict__ time_seq,         // [32,1024]
                 const float* __restrict__ q_bias,         // [10000]
                 const float* __restrict__ c_bias,         // [256]
                 float* __restrict__ out)                  // [32,1023]
{
    constexpr int SEQ = 1024;
    const float C0 = 0.62133497f;                  // 1/ln5

    extern __shared__ unsigned char smraw[];
    unsigned int* Gs = (unsigned int*)smraw;       // [NJ][RSJ]
    float2* tse = (float2*)(smraw + NJ * RSJ * 4); // [<=1024] (time, e*4 as int bits)
    float* jred = (float*)(tse + SEQ);             // [NJ]

    const int b   = blockIdx.y;
    const int j0  = ((int)gridDim.x - 1 - (int)blockIdx.x) * NJ;  // big tiles first
    const int tid = threadIdx.x;
    const int tj  = tid & (NJ - 1);                // 0..31  (warp lane)
    const int si  = tid >> 5;                      // 0..15  (uniform per warp)
    const int iend = j0 + NJ;

    // Stage (time, e*4 byte offset) for the i-range this CTA consumes
    for (int i = tid; i < iend; i += THREADS) {
        int g = b * SEQ + i;
        int e = concept_seq[g] + (correctness_seq[g] << 8);
        tse[i] = make_float2((float)time_seq[g], __int_as_float(e * 4));
    }
    if (tid < NJ) jred[tid] = 0.0f;

    // Gather packed rows: Gs[jl][e] <- g_pack[c_j][e]  (LDG.128 = 4 entries)
    for (int idx = tid; idx < NJ * 128; idx += THREADS) {
        int jl = idx >> 7;               // 0..31
        int q  = idx & 127;              // uint4 index (4 entries at e=4q)
        int cj = __ldg(concept_seq + b * SEQ + j0 + jl);
        uint4 v = ((const uint4*)(g_pack + cj * 512))[q];
        unsigned int* dst = Gs + jl * RSJ + 4 * q;
        dst[0] = v.x;  dst[1] = v.y;  dst[2] = v.z;  dst[3] = v.w;
    }
    __syncthreads();

    const int   jg   = j0 + tj;
    const float tjv  = tse[jg].x;
    const char* Grow = (const char*)(Gs + tj * RSJ);
    float jsum0 = 0.0f, jsum1 = 0.0f;

    // ---- Main region: i in [0, I0), no causal mask (I0 <= j0 <= jg) ----
    const int I0 = j0 & ~31;                        // multiple of 32
    const float4* tse4 = (const float4*)tse;        // pairs of (t, e4)
    const int kend = I0 >> 5;                       // each k covers i = 32k + 2si + {0,1}

    #pragma unroll 4
    for (int k = 0; k < kend; k++) {
        float4 tp = tse4[k * 16 + si];              // LDS.128, full-warp broadcast
        unsigned int u0 = *(const unsigned int*)(Grow + __float_as_int(tp.y));
        unsigned int u1 = *(const unsigned int*)(Grow + __float_as_int(tp.w));
        float ga0 = __uint_as_float(u0 & 0xFFFF0000u);   // bf16 high -> float (LOP3)
        float ga1 = __uint_as_float(u1 & 0xFFFF0000u);
        float d0  = __uint_as_float(u0 << 16);           // bf16 low  -> float (SHF)
        float d1  = __uint_as_float(u1 << 16);
        float lg0 = __log2f(fabsf(tp.x - tjv) + 1e-10f);
        float lg1 = __log2f(fabsf(tp.z - tjv) + 1e-10f);
        float a0  = fmaf(d0, lg0, -C0 * lg0);            // (d - C0) * lg
        float a1  = fmaf(d1, lg1, -C0 * lg1);
        jsum0 = fmaf(ga0, fast_ex2(a0), jsum0);
        jsum1 = fmaf(ga1, fast_ex2(a1), jsum1);
    }

    // ---- Tail: i in [I0, iend), masked i < jg (<= 64 i's -> <= 4 iterations) ----
    for (int i = I0 + si; i < iend; i += 16) {
        float2 tv = tse[i];
        unsigned int u = *(const unsigned int*)(Grow + __float_as_int(tv.y));
        float ga = __uint_as_float(u & 0xFFFF0000u);
        float d  = __uint_as_float(u << 16);
        float lg = __log2f(fabsf(tv.x - tjv) + 1e-10f);
        float ex = fast_ex2(fmaf(d, lg, -C0 * lg));
        jsum0 += (i < jg) ? ga * ex : 0.0f;
    }

    // Every lane owns a distinct tj within its warp -> spread smem atomics
    atomicAdd(&jred[tj], jsum0 + jsum1);
    __syncthreads();

    // Epilogue: bias + sigmoid; output drops j=0
    if (tid < NJ) {
        int j = j0 + tid;
        if (j > 0) {
            float x = q_bias[question_seq[b * SEQ + j]]
                    + c_bias[concept_seq[b * SEQ + j]]
                    + jred[tid];
            out[b * (SEQ - 1) + (j - 1)] = 1.0f / (1.0f + __expf(-x));
        }
    }
}

extern "C" void kernel_launch(void* const* d_in, const int* in_sizes, int n_in,
                              void* d_out, int out_size)
{
    (void)in_sizes; (void)n_in; (void)out_size;
    const int*   concept_seq     = (const int*)  d_in[0];
    const int*   question_seq    = (const int*)  d_in[1];
    const int*   correctness_seq = (const int*)  d_in[2];
    const int*   time_seq        = (const int*)  d_in[3];
    const float* a_inter         = (const float*)d_in[4];
    const float* a_concept       = (const float*)d_in[5];
    const float* b_inter         = (const float*)d_in[6];
    const float* b_concept       = (const float*)d_in[7];
    const float* q_bias          = (const float*)d_in[8];
    const float* c_bias          = (const float*)d_in[9];
    float* out = (float*)d_out;

    precompute_kernel<<<256, 256>>>(a_inter, a_concept, b_inter, b_concept);

    const int smem_bytes = NJ * RSJ * 4 + 1024 * 8 + NJ * 4;   // 74,240 B -> 3 CTAs/SM
    cudaFuncSetAttribute(hawkes_main,
                         cudaFuncAttributeMaxDynamicSharedMemorySize, smem_bytes);
    dim3 grid(1024 / NJ, 32);   // (j-tiles, batches) = (32, 32)
    hawkes_main<<<grid, THREADS, smem_bytes>>>(
        concept_seq, question_seq, correctness_seq, time_seq,
        q_bias, c_bias, out);
}